// round 3
// baseline (speedup 1.0000x reference)
#include <cuda_runtime.h>
#include <cstddef>

// ---------------------------------------------------------------------------
// GCN: 4x GraphConv (agg = adj@h ; h' = relu([h,agg]@W + b)) + PReLU head.
// B=32, N=1024, dims 256->512->512->256->256 -> PReLU(256) -> 2.
// Round-2 baseline: fp32 register-blocked SGEMM (128x128x8, 8x8/thread).
// ---------------------------------------------------------------------------

#define BATCH 32
#define SEQ   1024

#define BM 128
#define BN 128
#define BK 8
#define TM 8
#define TN 8
// 256 threads: 16x16 grid of 8x8 sub-tiles

// Scratch (allocation-free rule: __device__ globals). Max feature dim = 512.
__device__ float g_bufA[(size_t)BATCH * SEQ * 512];
__device__ float g_bufB[(size_t)BATCH * SEQ * 512];
__device__ float g_agg [(size_t)BATCH * SEQ * 512];

// ---------------------------------------------------------------------------
// Batched row-major SGEMM: C[b] = A[b] (MxK) * Bm[b] (KxNd).
// Used for agg = adj @ h.  M=K=1024, Nd in {256,512}. All dims multiples of 128/8.
// ---------------------------------------------------------------------------
__global__ __launch_bounds__(256) void sgemm_batched(
    const float* __restrict__ A, const float* __restrict__ Bm,
    float* __restrict__ C, int M, int K, int Nd)
{
    const int b = blockIdx.z;
    A  += (size_t)b * M * K;
    Bm += (size_t)b * K * Nd;
    C  += (size_t)b * M * Nd;

    __shared__ float As[BK][BM];   // transposed A tile
    __shared__ float Bs[BK][BN];

    const int tid = threadIdx.x;
    const int tx = tid & 15;       // 0..15 (col group)
    const int ty = tid >> 4;       // 0..15 (row group)
    const int rowBlock = blockIdx.y * BM;
    const int colBlock = blockIdx.x * BN;

    // global->smem load indices (float4)
    const int aRow  = tid >> 1;          // 0..127
    const int aCol4 = (tid & 1) * 4;     // 0 or 4
    const int bRow  = tid >> 5;          // 0..7
    const int bCol4 = (tid & 31) * 4;    // 0..124

    float acc[TM][TN] = {};

    for (int k0 = 0; k0 < K; k0 += BK) {
        float4 av = *reinterpret_cast<const float4*>(
            &A[(size_t)(rowBlock + aRow) * K + k0 + aCol4]);
        As[aCol4 + 0][aRow] = av.x;
        As[aCol4 + 1][aRow] = av.y;
        As[aCol4 + 2][aRow] = av.z;
        As[aCol4 + 3][aRow] = av.w;
        *reinterpret_cast<float4*>(&Bs[bRow][bCol4]) =
            *reinterpret_cast<const float4*>(
                &Bm[(size_t)(k0 + bRow) * Nd + colBlock + bCol4]);
        __syncthreads();

        #pragma unroll
        for (int kk = 0; kk < BK; kk++) {
            float ra[TM], rb[TN];
            *reinterpret_cast<float4*>(&ra[0]) = *reinterpret_cast<const float4*>(&As[kk][ty * TM]);
            *reinterpret_cast<float4*>(&ra[4]) = *reinterpret_cast<const float4*>(&As[kk][ty * TM + 4]);
            *reinterpret_cast<float4*>(&rb[0]) = *reinterpret_cast<const float4*>(&Bs[kk][tx * TN]);
            *reinterpret_cast<float4*>(&rb[4]) = *reinterpret_cast<const float4*>(&Bs[kk][tx * TN + 4]);
            #pragma unroll
            for (int i = 0; i < TM; i++)
                #pragma unroll
                for (int j = 0; j < TN; j++)
                    acc[i][j] = fmaf(ra[i], rb[j], acc[i][j]);
        }
        __syncthreads();
    }

    #pragma unroll
    for (int i = 0; i < TM; i++) {
        const size_t r = (size_t)(rowBlock + ty * TM + i) * Nd + colBlock + tx * TN;
        #pragma unroll
        for (int j = 0; j < TN; j += 4) {
            float4 v = make_float4(acc[i][j], acc[i][j+1], acc[i][j+2], acc[i][j+3]);
            *reinterpret_cast<float4*>(&C[r + j]) = v;
        }
    }
}

// ---------------------------------------------------------------------------
// Fused dense layer: C = act( X @ Wt + G @ Wb + bias )
//   X, G: [M, K] row-major.  Wt, Wb: [K, Nd] row-major.  G may be null.
//   act: 1 = relu, 2 = prelu(alpha per-channel), 0 = none.
// Implements cat([x,agg]) @ W without materializing the concat.
// ---------------------------------------------------------------------------
__global__ __launch_bounds__(256) void dense_kernel(
    const float* __restrict__ X, const float* __restrict__ G,
    const float* __restrict__ Wt, const float* __restrict__ Wb,
    const float* __restrict__ bias, const float* __restrict__ alpha,
    float* __restrict__ C, int M, int K, int Nd, int act)
{
    __shared__ float As[BK][BM];
    __shared__ float Bs[BK][BN];

    const int tid = threadIdx.x;
    const int tx = tid & 15;
    const int ty = tid >> 4;
    const int rowBlock = blockIdx.y * BM;
    const int colBlock = blockIdx.x * BN;

    const int aRow  = tid >> 1;
    const int aCol4 = (tid & 1) * 4;
    const int bRow  = tid >> 5;
    const int bCol4 = (tid & 31) * 4;

    float acc[TM][TN] = {};

    // pass 0: X @ Wt ; pass 1: G @ Wb
    for (int pass = 0; pass < 2; pass++) {
        const float* Ap = (pass == 0) ? X : G;
        const float* Wp = (pass == 0) ? Wt : Wb;
        if (Ap == nullptr) continue;
        for (int k0 = 0; k0 < K; k0 += BK) {
            float4 av = *reinterpret_cast<const float4*>(
                &Ap[(size_t)(rowBlock + aRow) * K + k0 + aCol4]);
            As[aCol4 + 0][aRow] = av.x;
            As[aCol4 + 1][aRow] = av.y;
            As[aCol4 + 2][aRow] = av.z;
            As[aCol4 + 3][aRow] = av.w;
            *reinterpret_cast<float4*>(&Bs[bRow][bCol4]) =
                *reinterpret_cast<const float4*>(
                    &Wp[(size_t)(k0 + bRow) * Nd + colBlock + bCol4]);
            __syncthreads();

            #pragma unroll
            for (int kk = 0; kk < BK; kk++) {
                float ra[TM], rb[TN];
                *reinterpret_cast<float4*>(&ra[0]) = *reinterpret_cast<const float4*>(&As[kk][ty * TM]);
                *reinterpret_cast<float4*>(&ra[4]) = *reinterpret_cast<const float4*>(&As[kk][ty * TM + 4]);
                *reinterpret_cast<float4*>(&rb[0]) = *reinterpret_cast<const float4*>(&Bs[kk][tx * TN]);
                *reinterpret_cast<float4*>(&rb[4]) = *reinterpret_cast<const float4*>(&Bs[kk][tx * TN + 4]);
                #pragma unroll
                for (int i = 0; i < TM; i++)
                    #pragma unroll
                    for (int j = 0; j < TN; j++)
                        acc[i][j] = fmaf(ra[i], rb[j], acc[i][j]);
            }
            __syncthreads();
        }
    }

    // epilogue: bias + activation
    float bj[TN], aj[TN];
    #pragma unroll
    for (int j = 0; j < TN; j++) {
        const int c = colBlock + tx * TN + j;
        bj[j] = bias[c];
        aj[j] = (act == 2) ? alpha[c] : 0.0f;
    }

    #pragma unroll
    for (int i = 0; i < TM; i++) {
        const size_t r = (size_t)(rowBlock + ty * TM + i) * Nd + colBlock + tx * TN;
        #pragma unroll
        for (int j = 0; j < TN; j += 4) {
            float v[4];
            #pragma unroll
            for (int q = 0; q < 4; q++) {
                float c = acc[i][j + q] + bj[j + q];
                if (act == 1)      c = fmaxf(c, 0.0f);
                else if (act == 2) c = (c > 0.0f) ? c : aj[j + q] * c;
                v[q] = c;
            }
            *reinterpret_cast<float4*>(&C[r + j]) = make_float4(v[0], v[1], v[2], v[3]);
        }
    }
}

// ---------------------------------------------------------------------------
// Head: out[r, 0:2] = T[r, :] @ cW2 (256x2) + cb2.  One warp per row.
// ---------------------------------------------------------------------------
__global__ __launch_bounds__(256) void head_kernel(
    const float* __restrict__ T, const float* __restrict__ W,
    const float* __restrict__ bvec, float* __restrict__ out, int M)
{
    const int warp = (blockIdx.x * blockDim.x + threadIdx.x) >> 5;
    const int lane = threadIdx.x & 31;
    if (warp >= M) return;
    const float* row = T + (size_t)warp * 256;
    float s0 = 0.0f, s1 = 0.0f;
    #pragma unroll
    for (int j0 = 0; j0 < 256; j0 += 32) {
        const int j = j0 + lane;
        const float v = row[j];
        s0 = fmaf(v, W[j * 2 + 0], s0);
        s1 = fmaf(v, W[j * 2 + 1], s1);
    }
    #pragma unroll
    for (int off = 16; off > 0; off >>= 1) {
        s0 += __shfl_down_sync(0xFFFFFFFFu, s0, off);
        s1 += __shfl_down_sync(0xFFFFFFFFu, s1, off);
    }
    if (lane == 0) {
        out[(size_t)warp * 2 + 0] = s0 + bvec[0];
        out[(size_t)warp * 2 + 1] = s1 + bvec[1];
    }
}

// ---------------------------------------------------------------------------
extern "C" void kernel_launch(void* const* d_in, const int* in_sizes, int n_in,
                              void* d_out, int out_size)
{
    (void)in_sizes; (void)n_in; (void)out_size;
    const float* x     = (const float*)d_in[0];
    const float* adj   = (const float*)d_in[1];
    const float* W1    = (const float*)d_in[2];
    const float* b1    = (const float*)d_in[3];
    const float* W2    = (const float*)d_in[4];
    const float* b2    = (const float*)d_in[5];
    const float* W3    = (const float*)d_in[6];
    const float* b3    = (const float*)d_in[7];
    const float* W4    = (const float*)d_in[8];
    const float* b4    = (const float*)d_in[9];
    const float* cW1   = (const float*)d_in[10];
    const float* cb1   = (const float*)d_in[11];
    const float* alpha = (const float*)d_in[12];
    const float* cW2   = (const float*)d_in[13];
    const float* cb2   = (const float*)d_in[14];
    float* out = (float*)d_out;

    float *hA, *hB, *ag;
    cudaGetSymbolAddress((void**)&hA, g_bufA);
    cudaGetSymbolAddress((void**)&hB, g_bufB);
    cudaGetSymbolAddress((void**)&ag, g_agg);

    const int M = BATCH * SEQ;   // 32768
    dim3 blk(256);

    // ---- Layer 1: d=256 -> 512
    sgemm_batched<<<dim3(256 / BN, SEQ / BM, BATCH), blk>>>(adj, x, ag, SEQ, SEQ, 256);
    dense_kernel<<<dim3(512 / BN, M / BM), blk>>>(
        x, ag, W1, W1 + 256 * 512, b1, nullptr, hA, M, 256, 512, 1);

    // ---- Layer 2: d=512 -> 512
    sgemm_batched<<<dim3(512 / BN, SEQ / BM, BATCH), blk>>>(adj, hA, ag, SEQ, SEQ, 512);
    dense_kernel<<<dim3(512 / BN, M / BM), blk>>>(
        hA, ag, W2, W2 + 512 * 512, b2, nullptr, hB, M, 512, 512, 1);

    // ---- Layer 3: d=512 -> 256
    sgemm_batched<<<dim3(512 / BN, SEQ / BM, BATCH), blk>>>(adj, hB, ag, SEQ, SEQ, 512);
    dense_kernel<<<dim3(256 / BN, M / BM), blk>>>(
        hB, ag, W3, W3 + 512 * 256, b3, nullptr, hA, M, 512, 256, 1);

    // ---- Layer 4: d=256 -> 256
    sgemm_batched<<<dim3(256 / BN, SEQ / BM, BATCH), blk>>>(adj, hA, ag, SEQ, SEQ, 256);
    dense_kernel<<<dim3(256 / BN, M / BM), blk>>>(
        hA, ag, W4, W4 + 256 * 256, b4, nullptr, hB, M, 256, 256, 1);

    // ---- Classifier: Linear(256,256) + PReLU, then Linear(256,2)
    dense_kernel<<<dim3(256 / BN, M / BM), blk>>>(
        hB, nullptr, cW1, nullptr, cb1, alpha, hA, M, 256, 256, 2);
    head_kernel<<<(M * 32 + 255) / 256, blk>>>(hA, cW2, cb2, out, M);
}

// round 5
// speedup vs baseline: 2.5163x; 2.5163x over previous
#include <cuda_runtime.h>
#include <cuda_bf16.h>
#include <cstdint>
#include <cstddef>

// ===========================================================================
// GCN via mma.sync bf16 tensor cores (sm_103 base target — no tcgen05 PTX),
// bf16x3 error compensation (AhBh + AhBl + AlBh), fp32 accumulators.
//   4x GraphConv:  agg = adj @ h ; h' = relu([h, agg] @ W + b)
//   classifier:    PReLU(h @ cW1 + cb1) @ cW2 + cb2
// ===========================================================================

#define BATCH 32
#define SEQ   1024

// ---------------- device scratch (allocation-free rule) --------------------
__device__ __nv_bfloat16 g_adjh[33554432], g_adjl[33554432];
__device__ __nv_bfloat16 g_Uh[16777216], g_Ul[16777216];   // activations ping
__device__ __nv_bfloat16 g_Vh[16777216], g_Vl[16777216];   // activations pong
__device__ __nv_bfloat16 g_Gh[16777216], g_Gl[16777216];   // aggregation
__device__ __nv_bfloat16 g_Wh[1245184],  g_Wl[1245184];    // all weights hi/lo
__device__ float         g_Cf[8388608];                    // classifier fp32

// ---------------- PTX helpers ----------------------------------------------
__device__ __forceinline__ uint32_t smem_u32(const void* p) {
    uint32_t a;
    asm("{ .reg .u64 t; cvta.to.shared.u64 t, %1; cvt.u32.u64 %0, t; }"
        : "=r"(a) : "l"(p));
    return a;
}
__device__ __forceinline__ void cp_async16(uint32_t dst, const void* src) {
    asm volatile("cp.async.cg.shared.global [%0], [%1], 16;"
                 :: "r"(dst), "l"(src));
}
#define CP_COMMIT() asm volatile("cp.async.commit_group;" ::: "memory")
#define CP_WAIT1()  asm volatile("cp.async.wait_group 1;" ::: "memory")
#define CP_WAIT0()  asm volatile("cp.async.wait_group 0;" ::: "memory")

__device__ __forceinline__ void ldsm4(uint32_t* d, uint32_t a) {
    asm volatile("ldmatrix.sync.aligned.m8n8.x4.shared.b16 {%0,%1,%2,%3}, [%4];"
                 : "=r"(d[0]), "=r"(d[1]), "=r"(d[2]), "=r"(d[3]) : "r"(a));
}
__device__ __forceinline__ void ldsm4t(uint32_t* d, uint32_t a) {
    asm volatile("ldmatrix.sync.aligned.m8n8.x4.trans.shared.b16 {%0,%1,%2,%3}, [%4];"
                 : "=r"(d[0]), "=r"(d[1]), "=r"(d[2]), "=r"(d[3]) : "r"(a));
}
__device__ __forceinline__ void mma16816(float* c, const uint32_t* a,
                                         uint32_t b0, uint32_t b1) {
    asm volatile(
        "mma.sync.aligned.m16n8k16.row.col.f32.bf16.bf16.f32 "
        "{%0,%1,%2,%3}, {%4,%5,%6,%7}, {%8,%9}, {%0,%1,%2,%3};"
        : "+f"(c[0]), "+f"(c[1]), "+f"(c[2]), "+f"(c[3])
        : "r"(a[0]), "r"(a[1]), "r"(a[2]), "r"(a[3]), "r"(b0), "r"(b1));
}

// ---------------- smem layout constants -------------------------------------
// Per stage: A hi/lo 128x32 (row stride 80B), B hi/lo 32x128 (row stride 272B)
#define A_STRIDE 80
#define B_STRIDE 272
#define AH_OFF   0
#define AL_OFF   10240
#define BH_OFF   20480
#define BL_OFF   29184
#define STAGE_SZ 37888
#define SMEM_SZ  (2 * STAGE_SZ)

// ---------------------------------------------------------------------------
// Unified bf16x3 GEMM tile kernel. 128x128 output tile, K in 32-chunks.
//   pass0: A0 x B0   (A0 [rows x K0] row-major, B0 [K0 x Nd] row-major)
//   pass1: + A1 x B1 (optional, K1>0)  -> implements X@Wt + G@Wb (concat GEMM)
//   epilogue: +bias / relu / prelu; writes hi/lo bf16 row-major, or fp32.
// ---------------------------------------------------------------------------
__global__ __launch_bounds__(256, 1) void gemm_mma(
    const __nv_bfloat16* __restrict__ A0h, const __nv_bfloat16* __restrict__ A0l,
    size_t a0B, int lda0, int K0,
    const __nv_bfloat16* __restrict__ B0h, const __nv_bfloat16* __restrict__ B0l,
    size_t b0B, int ldb0,
    const __nv_bfloat16* __restrict__ A1h, const __nv_bfloat16* __restrict__ A1l,
    int lda1, int K1,
    const __nv_bfloat16* __restrict__ B1h, const __nv_bfloat16* __restrict__ B1l,
    int ldb1,
    const float* __restrict__ bias, const float* __restrict__ alphaP, int act,
    __nv_bfloat16* __restrict__ outH, __nv_bfloat16* __restrict__ outL,
    float* __restrict__ outF, int Nd, int rowsPerBatch)
{
    extern __shared__ char smem[];
    const uint32_t sb = smem_u32(smem);
    const int tid  = threadIdx.x;
    const int wid  = tid >> 5, lane = tid & 31;
    const int z    = blockIdx.z;
    const int colBlock = blockIdx.x * 128;
    const size_t gRow0 = (size_t)z * rowsPerBatch + (size_t)blockIdx.y * 128;

    const __nv_bfloat16* a0H = A0h + z * a0B + (size_t)(blockIdx.y * 128) * lda0;
    const __nv_bfloat16* a0L = A0l + z * a0B + (size_t)(blockIdx.y * 128) * lda0;
    const __nv_bfloat16* b0H = B0h + z * b0B;
    const __nv_bfloat16* b0L = B0l + z * b0B;
    const __nv_bfloat16* a1H = A1h ? A1h + gRow0 * lda1 : nullptr;
    const __nv_bfloat16* a1L = A1l ? A1l + gRow0 * lda1 : nullptr;

    const int n0 = K0 >> 5;                  // chunks in pass 0
    const int nChunks = n0 + (K1 >> 5);

    // thread's load indices
    const int aR = tid >> 1;                       // wrong granularity? no:
    // A tile: 512 16B-loads -> 2/thread: idx = tid + i*256, row = idx>>2, c = idx&3
    // B tile: 512 16B-loads -> 2/thread: row = idx>>4, c = idx&15

    auto issue_loads = [&](int c) {
        const int s = c & 1;
        const uint32_t so = sb + s * STAGE_SZ;
        const int pass = (c < n0) ? 0 : 1;
        const int k0 = (pass ? (c - n0) : c) << 5;
        const __nv_bfloat16* aH = pass ? a1H : a0H;
        const __nv_bfloat16* aL = pass ? a1L : a0L;
        const __nv_bfloat16* bH = pass ? B1h : b0H;
        const __nv_bfloat16* bL = pass ? B1l : b0L;
        const int lA = pass ? lda1 : lda0;
        const int lB = pass ? ldb1 : ldb0;
        #pragma unroll
        for (int i = 0; i < 2; i++) {
            const int idx = tid + i * 256;
            const int r = idx >> 2, cc = idx & 3;
            const size_t gsrc = (size_t)r * lA + k0 + cc * 8;
            cp_async16(so + AH_OFF + r * A_STRIDE + cc * 16, aH + gsrc);
            cp_async16(so + AL_OFF + r * A_STRIDE + cc * 16, aL + gsrc);
        }
        #pragma unroll
        for (int i = 0; i < 2; i++) {
            const int idx = tid + i * 256;
            const int r = idx >> 4, cc = idx & 15;
            const size_t gsrc = (size_t)(k0 + r) * lB + colBlock + cc * 8;
            cp_async16(so + BH_OFF + r * B_STRIDE + cc * 16, bH + gsrc);
            cp_async16(so + BL_OFF + r * B_STRIDE + cc * 16, bL + gsrc);
        }
        CP_COMMIT();
    };

    float acc[4][4][4];
    #pragma unroll
    for (int i = 0; i < 4; i++)
        #pragma unroll
        for (int j = 0; j < 4; j++)
            #pragma unroll
            for (int q = 0; q < 4; q++) acc[i][j][q] = 0.0f;

    issue_loads(0);
    if (nChunks > 1) issue_loads(1);

    const int warpM = wid >> 2;          // 0..1 -> m offset 0/64
    const int warpN = wid & 3;           // 0..3 -> n offset 0/32/64/96
    const int mBase = warpM * 64;
    const int nBase = warpN * 32;
    const int lr  = lane & 15;           // ldmatrix row select
    const int lc8 = (lane >> 4) * 8;     // ldmatrix col-8 select

    for (int c = 0; c < nChunks; c++) {
        if (c + 1 < nChunks) CP_WAIT1(); else CP_WAIT0();
        __syncthreads();
        const uint32_t so = sb + (c & 1) * STAGE_SZ;

        #pragma unroll
        for (int kt = 0; kt < 2; kt++) {
            const int kb = kt * 16;
            uint32_t aH[4][4], aL[4][4], bH[2][4], bL[2][4];
            #pragma unroll
            for (int mt = 0; mt < 4; mt++) {
                const uint32_t ad = so + AH_OFF +
                    (mBase + mt * 16 + lr) * A_STRIDE + (kb + lc8) * 2;
                ldsm4(aH[mt], ad);
                ldsm4(aL[mt], ad + (AL_OFF - AH_OFF));
            }
            #pragma unroll
            for (int nb = 0; nb < 2; nb++) {
                const uint32_t bd = so + BH_OFF +
                    (kb + lr) * B_STRIDE + (nBase + nb * 16 + lc8) * 2;
                ldsm4t(bH[nb], bd);
                ldsm4t(bL[nb], bd + (BL_OFF - BH_OFF));
            }
            #pragma unroll
            for (int mt = 0; mt < 4; mt++)
                #pragma unroll
                for (int n8 = 0; n8 < 4; n8++) {
                    const int nb = n8 >> 1, w = (n8 & 1) * 2;
                    mma16816(acc[mt][n8], aH[mt], bH[nb][w], bH[nb][w + 1]);
                    mma16816(acc[mt][n8], aH[mt], bL[nb][w], bL[nb][w + 1]);
                    mma16816(acc[mt][n8], aL[mt], bH[nb][w], bH[nb][w + 1]);
                }
        }
        __syncthreads();
        if (c + 2 < nChunks) issue_loads(c + 2);
    }

    // ---------------- epilogue ------------------------------------------------
    #pragma unroll
    for (int mt = 0; mt < 4; mt++) {
        #pragma unroll
        for (int half = 0; half < 2; half++) {
            const size_t grow = gRow0 + mBase + mt * 16 + (lane >> 2) + half * 8;
            #pragma unroll
            for (int n8 = 0; n8 < 4; n8++) {
                const int col = colBlock + nBase + n8 * 8 + 2 * (lane & 3);
                float v0 = acc[mt][n8][half * 2 + 0];
                float v1 = acc[mt][n8][half * 2 + 1];
                if (bias) { v0 += bias[col]; v1 += bias[col + 1]; }
                if (act == 1) {
                    v0 = fmaxf(v0, 0.0f); v1 = fmaxf(v1, 0.0f);
                } else if (act == 2) {
                    v0 = (v0 > 0.0f) ? v0 : alphaP[col] * v0;
                    v1 = (v1 > 0.0f) ? v1 : alphaP[col + 1] * v1;
                }
                if (outF) {
                    *reinterpret_cast<float2*>(outF + grow * Nd + col) =
                        make_float2(v0, v1);
                } else {
                    __nv_bfloat162 hv = __floats2bfloat162_rn(v0, v1);
                    float l0 = v0 - __bfloat162float(hv.x);
                    float l1 = v1 - __bfloat162float(hv.y);
                    __nv_bfloat162 lv = __floats2bfloat162_rn(l0, l1);
                    *reinterpret_cast<__nv_bfloat162*>(outH + grow * Nd + col) = hv;
                    *reinterpret_cast<__nv_bfloat162*>(outL + grow * Nd + col) = lv;
                }
            }
        }
    }
}

// ---------------------------------------------------------------------------
// fp32 -> (hi, lo) bf16 split, vectorized grid-stride
// ---------------------------------------------------------------------------
__global__ void split_kernel(const float* __restrict__ in,
                             __nv_bfloat16* __restrict__ h,
                             __nv_bfloat16* __restrict__ l, int n4)
{
    for (int i = blockIdx.x * blockDim.x + threadIdx.x; i < n4;
         i += gridDim.x * blockDim.x) {
        float4 v = reinterpret_cast<const float4*>(in)[i];
        float vv[4] = {v.x, v.y, v.z, v.w};
        __nv_bfloat16 hh[4], ll[4];
        #pragma unroll
        for (int q = 0; q < 4; q++) {
            hh[q] = __float2bfloat16(vv[q]);
            ll[q] = __float2bfloat16(vv[q] - __bfloat162float(hh[q]));
        }
        *reinterpret_cast<uint2*>(h + (size_t)i * 4) = *reinterpret_cast<uint2*>(hh);
        *reinterpret_cast<uint2*>(l + (size_t)i * 4) = *reinterpret_cast<uint2*>(ll);
    }
}

// ---------------------------------------------------------------------------
// Head: out[r, 0:2] = T[r, :] @ cW2 (256x2) + cb2.  One warp per row.
// ---------------------------------------------------------------------------
__global__ __launch_bounds__(256) void head_kernel(
    const float* __restrict__ T, const float* __restrict__ W,
    const float* __restrict__ bvec, float* __restrict__ out, int M)
{
    const int warp = (blockIdx.x * blockDim.x + threadIdx.x) >> 5;
    const int lane = threadIdx.x & 31;
    if (warp >= M) return;
    const float* row = T + (size_t)warp * 256;
    float s0 = 0.0f, s1 = 0.0f;
    #pragma unroll
    for (int j0 = 0; j0 < 256; j0 += 32) {
        const float v = row[j0 + lane];
        s0 = fmaf(v, W[(j0 + lane) * 2 + 0], s0);
        s1 = fmaf(v, W[(j0 + lane) * 2 + 1], s1);
    }
    #pragma unroll
    for (int off = 16; off > 0; off >>= 1) {
        s0 += __shfl_down_sync(0xFFFFFFFFu, s0, off);
        s1 += __shfl_down_sync(0xFFFFFFFFu, s1, off);
    }
    if (lane == 0) {
        out[(size_t)warp * 2 + 0] = s0 + bvec[0];
        out[(size_t)warp * 2 + 1] = s1 + bvec[1];
    }
}

// ---------------------------------------------------------------------------
extern "C" void kernel_launch(void* const* d_in, const int* in_sizes, int n_in,
                              void* d_out, int out_size)
{
    (void)in_sizes; (void)n_in; (void)out_size;
    const float* x     = (const float*)d_in[0];
    const float* adj   = (const float*)d_in[1];
    const float* W1    = (const float*)d_in[2];
    const float* b1    = (const float*)d_in[3];
    const float* W2    = (const float*)d_in[4];
    const float* b2    = (const float*)d_in[5];
    const float* W3    = (const float*)d_in[6];
    const float* b3    = (const float*)d_in[7];
    const float* W4    = (const float*)d_in[8];
    const float* b4    = (const float*)d_in[9];
    const float* cW1   = (const float*)d_in[10];
    const float* cb1   = (const float*)d_in[11];
    const float* alpha = (const float*)d_in[12];
    const float* cW2   = (const float*)d_in[13];
    const float* cb2   = (const float*)d_in[14];
    float* out = (float*)d_out;

    __nv_bfloat16 *adjh, *adjl, *Uh, *Ul, *Vh, *Vl, *Gh, *Gl, *Wh, *Wl;
    float* Cf;
    cudaGetSymbolAddress((void**)&adjh, g_adjh);
    cudaGetSymbolAddress((void**)&adjl, g_adjl);
    cudaGetSymbolAddress((void**)&Uh, g_Uh); cudaGetSymbolAddress((void**)&Ul, g_Ul);
    cudaGetSymbolAddress((void**)&Vh, g_Vh); cudaGetSymbolAddress((void**)&Vl, g_Vl);
    cudaGetSymbolAddress((void**)&Gh, g_Gh); cudaGetSymbolAddress((void**)&Gl, g_Gl);
    cudaGetSymbolAddress((void**)&Wh, g_Wh); cudaGetSymbolAddress((void**)&Wl, g_Wl);
    cudaGetSymbolAddress((void**)&Cf, g_Cf);

    cudaFuncSetAttribute(gemm_mma, cudaFuncAttributeMaxDynamicSharedMemorySize,
                         SMEM_SZ);
    dim3 blk(256);

    // ---- operand splits (fp32 -> hi/lo bf16; no transposes needed) ----
    split_kernel<<<2048, blk>>>(adj, adjh, adjl, 8388608);
    split_kernel<<<1024, blk>>>(x, Uh, Ul, 2097152);
    split_kernel<<<256, blk>>>(W1,  Wh,           Wl,           65536);
    split_kernel<<<512, blk>>>(W2,  Wh + 262144,  Wl + 262144,  131072);
    split_kernel<<<256, blk>>>(W3,  Wh + 786432,  Wl + 786432,  65536);
    split_kernel<<<128, blk>>>(W4,  Wh + 1048576, Wl + 1048576, 32768);
    split_kernel<<<64,  blk>>>(cW1, Wh + 1179648, Wl + 1179648, 16384);

    const size_t ADJB = 1048576;   // 1024*1024 per batch
    const int M = BATCH * SEQ;     // 32768

    // ---- Layer 1 (256 -> 512) ----
    gemm_mma<<<dim3(2, 8, 32), blk, SMEM_SZ>>>(
        adjh, adjl, ADJB, 1024, 1024, Uh, Ul, (size_t)1024 * 256, 256,
        nullptr, nullptr, 0, 0, nullptr, nullptr, 0,
        nullptr, nullptr, 0, Gh, Gl, nullptr, 256, 1024);
    gemm_mma<<<dim3(4, 256, 1), blk, SMEM_SZ>>>(
        Uh, Ul, 0, 256, 256, Wh, Wl, 0, 512,
        Gh, Gl, 256, 256, Wh + 131072, Wl + 131072, 512,
        b1, nullptr, 1, Vh, Vl, nullptr, 512, M);

    // ---- Layer 2 (512 -> 512) ----
    gemm_mma<<<dim3(4, 8, 32), blk, SMEM_SZ>>>(
        adjh, adjl, ADJB, 1024, 1024, Vh, Vl, (size_t)1024 * 512, 512,
        nullptr, nullptr, 0, 0, nullptr, nullptr, 0,
        nullptr, nullptr, 0, Gh, Gl, nullptr, 512, 1024);
    gemm_mma<<<dim3(4, 256, 1), blk, SMEM_SZ>>>(
        Vh, Vl, 0, 512, 512, Wh + 262144, Wl + 262144, 0, 512,
        Gh, Gl, 512, 512, Wh + 524288, Wl + 524288, 512,
        b2, nullptr, 1, Uh, Ul, nullptr, 512, M);

    // ---- Layer 3 (512 -> 256) ----
    gemm_mma<<<dim3(4, 8, 32), blk, SMEM_SZ>>>(
        adjh, adjl, ADJB, 1024, 1024, Uh, Ul, (size_t)1024 * 512, 512,
        nullptr, nullptr, 0, 0, nullptr, nullptr, 0,
        nullptr, nullptr, 0, Gh, Gl, nullptr, 512, 1024);
    gemm_mma<<<dim3(2, 256, 1), blk, SMEM_SZ>>>(
        Uh, Ul, 0, 512, 512, Wh + 786432, Wl + 786432, 0, 256,
        Gh, Gl, 512, 512, Wh + 917504, Wl + 917504, 256,
        b3, nullptr, 1, Vh, Vl, nullptr, 256, M);

    // ---- Layer 4 (256 -> 256) ----
    gemm_mma<<<dim3(2, 8, 32), blk, SMEM_SZ>>>(
        adjh, adjl, ADJB, 1024, 1024, Vh, Vl, (size_t)1024 * 256, 256,
        nullptr, nullptr, 0, 0, nullptr, nullptr, 0,
        nullptr, nullptr, 0, Gh, Gl, nullptr, 256, 1024);
    gemm_mma<<<dim3(2, 256, 1), blk, SMEM_SZ>>>(
        Vh, Vl, 0, 256, 256, Wh + 1048576, Wl + 1048576, 0, 256,
        Gh, Gl, 256, 256, Wh + 1114112, Wl + 1114112, 256,
        b4, nullptr, 1, Uh, Ul, nullptr, 256, M);

    // ---- classifier: Linear + PReLU (fp32 out), then 256->2 head ----
    gemm_mma<<<dim3(2, 256, 1), blk, SMEM_SZ>>>(
        Uh, Ul, 0, 256, 256, Wh + 1179648, Wl + 1179648, 0, 256,
        nullptr, nullptr, 0, 0, nullptr, nullptr, 0,
        cb1, alpha, 2, nullptr, nullptr, Cf, 256, M);
    head_kernel<<<(M * 32 + 255) / 256, blk>>>(Cf, cW2, cb2, out, M);
}

// round 6
// speedup vs baseline: 2.7378x; 1.0880x over previous
#include <cuda_runtime.h>
#include <cuda_bf16.h>
#include <cstdint>
#include <cstddef>

// ===========================================================================
// GCN via mma.sync bf16 tensor cores, bf16x3 compensation, fp32 accumulators.
// R6: term-outermost MMA order (no dependent HMMA chains), 3-stage cp.async
// pipeline with single barrier per chunk, layer-3 reassociation.
// ===========================================================================

#define BATCH 32
#define SEQ   1024

// ---------------- device scratch (allocation-free rule) --------------------
__device__ __nv_bfloat16 g_adjh[33554432], g_adjl[33554432];
__device__ __nv_bfloat16 g_Uh[16777216], g_Ul[16777216];   // activations ping
__device__ __nv_bfloat16 g_Vh[16777216], g_Vl[16777216];   // activations pong
__device__ __nv_bfloat16 g_Gh[16777216], g_Gl[16777216];   // aggregation / P
__device__ __nv_bfloat16 g_Wh[1245184],  g_Wl[1245184];    // all weights hi/lo
__device__ float         g_Cf[8388608];                    // classifier fp32

// ---------------- PTX helpers ----------------------------------------------
__device__ __forceinline__ uint32_t smem_u32(const void* p) {
    uint32_t a;
    asm("{ .reg .u64 t; cvta.to.shared.u64 t, %1; cvt.u32.u64 %0, t; }"
        : "=r"(a) : "l"(p));
    return a;
}
__device__ __forceinline__ void cp_async16(uint32_t dst, const void* src) {
    asm volatile("cp.async.cg.shared.global [%0], [%1], 16;"
                 :: "r"(dst), "l"(src));
}
#define CP_COMMIT() asm volatile("cp.async.commit_group;" ::: "memory")
#define CP_WAIT1()  asm volatile("cp.async.wait_group 1;" ::: "memory")
#define CP_WAIT0()  asm volatile("cp.async.wait_group 0;" ::: "memory")

__device__ __forceinline__ void ldsm4(uint32_t* d, uint32_t a) {
    asm volatile("ldmatrix.sync.aligned.m8n8.x4.shared.b16 {%0,%1,%2,%3}, [%4];"
                 : "=r"(d[0]), "=r"(d[1]), "=r"(d[2]), "=r"(d[3]) : "r"(a));
}
__device__ __forceinline__ void ldsm4t(uint32_t* d, uint32_t a) {
    asm volatile("ldmatrix.sync.aligned.m8n8.x4.trans.shared.b16 {%0,%1,%2,%3}, [%4];"
                 : "=r"(d[0]), "=r"(d[1]), "=r"(d[2]), "=r"(d[3]) : "r"(a));
}
__device__ __forceinline__ void mma16816(float* c, const uint32_t* a,
                                         uint32_t b0, uint32_t b1) {
    asm volatile(
        "mma.sync.aligned.m16n8k16.row.col.f32.bf16.bf16.f32 "
        "{%0,%1,%2,%3}, {%4,%5,%6,%7}, {%8,%9}, {%0,%1,%2,%3};"
        : "+f"(c[0]), "+f"(c[1]), "+f"(c[2]), "+f"(c[3])
        : "r"(a[0]), "r"(a[1]), "r"(a[2]), "r"(a[3]), "r"(b0), "r"(b1));
}

// ---------------- smem layout constants -------------------------------------
#define A_STRIDE 80
#define B_STRIDE 272
#define AH_OFF   0
#define AL_OFF   10240
#define BH_OFF   20480
#define BL_OFF   29184
#define STAGE_SZ 37888
#define STAGES   3
#define SMEM_SZ  (STAGES * STAGE_SZ)

// ---------------------------------------------------------------------------
// Unified bf16x3 GEMM tile kernel. 128x128 output tile, K in 32-chunks.
//   pass0: A0 x B0 ; pass1 (K1>0): + A1 x B1   (concat GEMM / fused add)
//   epilogue: +bias / relu / prelu; writes hi/lo bf16, or fp32.
// ---------------------------------------------------------------------------
__global__ __launch_bounds__(256, 1) void gemm_mma(
    const __nv_bfloat16* __restrict__ A0h, const __nv_bfloat16* __restrict__ A0l,
    size_t a0B, int lda0, int K0,
    const __nv_bfloat16* __restrict__ B0h, const __nv_bfloat16* __restrict__ B0l,
    size_t b0B, int ldb0,
    const __nv_bfloat16* __restrict__ A1h, const __nv_bfloat16* __restrict__ A1l,
    int lda1, int K1,
    const __nv_bfloat16* __restrict__ B1h, const __nv_bfloat16* __restrict__ B1l,
    int ldb1,
    const float* __restrict__ bias, const float* __restrict__ alphaP, int act,
    __nv_bfloat16* __restrict__ outH, __nv_bfloat16* __restrict__ outL,
    float* __restrict__ outF, int Nd, int rowsPerBatch)
{
    extern __shared__ char smem[];
    const uint32_t sb = smem_u32(smem);
    const int tid  = threadIdx.x;
    const int wid  = tid >> 5, lane = tid & 31;
    const int z    = blockIdx.z;
    const int colBlock = blockIdx.x * 128;
    const size_t gRow0 = (size_t)z * rowsPerBatch + (size_t)blockIdx.y * 128;

    const __nv_bfloat16* a0H = A0h + z * a0B + (size_t)(blockIdx.y * 128) * lda0;
    const __nv_bfloat16* a0L = A0l + z * a0B + (size_t)(blockIdx.y * 128) * lda0;
    const __nv_bfloat16* b0H = B0h + z * b0B;
    const __nv_bfloat16* b0L = B0l + z * b0B;
    const __nv_bfloat16* a1H = A1h ? A1h + gRow0 * lda1 : nullptr;
    const __nv_bfloat16* a1L = A1l ? A1l + gRow0 * lda1 : nullptr;

    const int n0 = K0 >> 5;
    const int nChunks = n0 + (K1 >> 5);

    auto issue_loads = [&](int c) {
        const uint32_t so = sb + (c % STAGES) * STAGE_SZ;
        const int pass = (c < n0) ? 0 : 1;
        const int k0 = (pass ? (c - n0) : c) << 5;
        const __nv_bfloat16* aH = pass ? a1H : a0H;
        const __nv_bfloat16* aL = pass ? a1L : a0L;
        const __nv_bfloat16* bH = pass ? B1h : b0H;
        const __nv_bfloat16* bL = pass ? B1l : b0L;
        const int lA = pass ? lda1 : lda0;
        const int lB = pass ? ldb1 : ldb0;
        #pragma unroll
        for (int i = 0; i < 2; i++) {
            const int idx = tid + i * 256;
            const int r = idx >> 2, cc = idx & 3;
            const size_t gsrc = (size_t)r * lA + k0 + cc * 8;
            cp_async16(so + AH_OFF + r * A_STRIDE + cc * 16, aH + gsrc);
            cp_async16(so + AL_OFF + r * A_STRIDE + cc * 16, aL + gsrc);
        }
        #pragma unroll
        for (int i = 0; i < 2; i++) {
            const int idx = tid + i * 256;
            const int r = idx >> 4, cc = idx & 15;
            const size_t gsrc = (size_t)(k0 + r) * lB + colBlock + cc * 8;
            cp_async16(so + BH_OFF + r * B_STRIDE + cc * 16, bH + gsrc);
            cp_async16(so + BL_OFF + r * B_STRIDE + cc * 16, bL + gsrc);
        }
        CP_COMMIT();
    };

    float acc[4][4][4];
    #pragma unroll
    for (int i = 0; i < 4; i++)
        #pragma unroll
        for (int j = 0; j < 4; j++)
            #pragma unroll
            for (int q = 0; q < 4; q++) acc[i][j][q] = 0.0f;

    issue_loads(0);
    if (nChunks > 1) issue_loads(1);

    const int warpM = wid >> 2;
    const int warpN = wid & 3;
    const int mBase = warpM * 64;
    const int nBase = warpN * 32;
    const int lr  = lane & 15;
    const int lc8 = (lane >> 4) * 8;

    for (int c = 0; c < nChunks; c++) {
        if (c + 1 < nChunks) CP_WAIT1(); else CP_WAIT0();
        __syncthreads();
        if (c + 2 < nChunks) issue_loads(c + 2);
        const uint32_t so = sb + (c % STAGES) * STAGE_SZ;

        #pragma unroll
        for (int kt = 0; kt < 2; kt++) {
            const int kb = kt * 16;
            uint32_t aH[4][4], aL[4][4], bH[2][4], bL[2][4];
            #pragma unroll
            for (int mt = 0; mt < 4; mt++) {
                const uint32_t ad = so + AH_OFF +
                    (mBase + mt * 16 + lr) * A_STRIDE + (kb + lc8) * 2;
                ldsm4(aH[mt], ad);
                ldsm4(aL[mt], ad + (AL_OFF - AH_OFF));
            }
            #pragma unroll
            for (int nb = 0; nb < 2; nb++) {
                const uint32_t bd = so + BH_OFF +
                    (kb + lr) * B_STRIDE + (nBase + nb * 16 + lc8) * 2;
                ldsm4t(bH[nb], bd);
                ldsm4t(bL[nb], bd + (BL_OFF - BH_OFF));
            }
            // term-outermost: 16 independent MMAs between acc reuses
            #pragma unroll
            for (int mt = 0; mt < 4; mt++)
                #pragma unroll
                for (int n8 = 0; n8 < 4; n8++) {
                    const int nb = n8 >> 1, w = (n8 & 1) * 2;
                    mma16816(acc[mt][n8], aH[mt], bH[nb][w], bH[nb][w + 1]);
                }
            #pragma unroll
            for (int mt = 0; mt < 4; mt++)
                #pragma unroll
                for (int n8 = 0; n8 < 4; n8++) {
                    const int nb = n8 >> 1, w = (n8 & 1) * 2;
                    mma16816(acc[mt][n8], aH[mt], bL[nb][w], bL[nb][w + 1]);
                }
            #pragma unroll
            for (int mt = 0; mt < 4; mt++)
                #pragma unroll
                for (int n8 = 0; n8 < 4; n8++) {
                    const int nb = n8 >> 1, w = (n8 & 1) * 2;
                    mma16816(acc[mt][n8], aL[mt], bH[nb][w], bH[nb][w + 1]);
                }
        }
    }

    // ---------------- epilogue ----------------------------------------------
    #pragma unroll
    for (int mt = 0; mt < 4; mt++) {
        #pragma unroll
        for (int half = 0; half < 2; half++) {
            const size_t grow = gRow0 + mBase + mt * 16 + (lane >> 2) + half * 8;
            #pragma unroll
            for (int n8 = 0; n8 < 4; n8++) {
                const int col = colBlock + nBase + n8 * 8 + 2 * (lane & 3);
                float v0 = acc[mt][n8][half * 2 + 0];
                float v1 = acc[mt][n8][half * 2 + 1];
                if (bias) { v0 += bias[col]; v1 += bias[col + 1]; }
                if (act == 1) {
                    v0 = fmaxf(v0, 0.0f); v1 = fmaxf(v1, 0.0f);
                } else if (act == 2) {
                    v0 = (v0 > 0.0f) ? v0 : alphaP[col] * v0;
                    v1 = (v1 > 0.0f) ? v1 : alphaP[col + 1] * v1;
                }
                if (outF) {
                    *reinterpret_cast<float2*>(outF + grow * Nd + col) =
                        make_float2(v0, v1);
                } else {
                    __nv_bfloat162 hv = __floats2bfloat162_rn(v0, v1);
                    float l0 = v0 - __bfloat162float(hv.x);
                    float l1 = v1 - __bfloat162float(hv.y);
                    __nv_bfloat162 lv = __floats2bfloat162_rn(l0, l1);
                    *reinterpret_cast<__nv_bfloat162*>(outH + grow * Nd + col) = hv;
                    *reinterpret_cast<__nv_bfloat162*>(outL + grow * Nd + col) = lv;
                }
            }
        }
    }
}

// ---------------------------------------------------------------------------
__global__ void split_kernel(const float* __restrict__ in,
                             __nv_bfloat16* __restrict__ h,
                             __nv_bfloat16* __restrict__ l, int n4)
{
    for (int i = blockIdx.x * blockDim.x + threadIdx.x; i < n4;
         i += gridDim.x * blockDim.x) {
        float4 v = reinterpret_cast<const float4*>(in)[i];
        float vv[4] = {v.x, v.y, v.z, v.w};
        __nv_bfloat16 hh[4], ll[4];
        #pragma unroll
        for (int q = 0; q < 4; q++) {
            hh[q] = __float2bfloat16(vv[q]);
            ll[q] = __float2bfloat16(vv[q] - __bfloat162float(hh[q]));
        }
        *reinterpret_cast<uint2*>(h + (size_t)i * 4) = *reinterpret_cast<uint2*>(hh);
        *reinterpret_cast<uint2*>(l + (size_t)i * 4) = *reinterpret_cast<uint2*>(ll);
    }
}

// ---------------------------------------------------------------------------
__global__ __launch_bounds__(256) void head_kernel(
    const float* __restrict__ T, const float* __restrict__ W,
    const float* __restrict__ bvec, float* __restrict__ out, int M)
{
    const int warp = (blockIdx.x * blockDim.x + threadIdx.x) >> 5;
    const int lane = threadIdx.x & 31;
    if (warp >= M) return;
    const float* row = T + (size_t)warp * 256;
    float s0 = 0.0f, s1 = 0.0f;
    #pragma unroll
    for (int j0 = 0; j0 < 256; j0 += 32) {
        const float v = row[j0 + lane];
        s0 = fmaf(v, W[(j0 + lane) * 2 + 0], s0);
        s1 = fmaf(v, W[(j0 + lane) * 2 + 1], s1);
    }
    #pragma unroll
    for (int off = 16; off > 0; off >>= 1) {
        s0 += __shfl_down_sync(0xFFFFFFFFu, s0, off);
        s1 += __shfl_down_sync(0xFFFFFFFFu, s1, off);
    }
    if (lane == 0) {
        out[(size_t)warp * 2 + 0] = s0 + bvec[0];
        out[(size_t)warp * 2 + 1] = s1 + bvec[1];
    }
}

// ---------------------------------------------------------------------------
extern "C" void kernel_launch(void* const* d_in, const int* in_sizes, int n_in,
                              void* d_out, int out_size)
{
    (void)in_sizes; (void)n_in; (void)out_size;
    const float* x     = (const float*)d_in[0];
    const float* adj   = (const float*)d_in[1];
    const float* W1    = (const float*)d_in[2];
    const float* b1    = (const float*)d_in[3];
    const float* W2    = (const float*)d_in[4];
    const float* b2    = (const float*)d_in[5];
    const float* W3    = (const float*)d_in[6];
    const float* b3    = (const float*)d_in[7];
    const float* W4    = (const float*)d_in[8];
    const float* b4    = (const float*)d_in[9];
    const float* cW1   = (const float*)d_in[10];
    const float* cb1   = (const float*)d_in[11];
    const float* alpha = (const float*)d_in[12];
    const float* cW2   = (const float*)d_in[13];
    const float* cb2   = (const float*)d_in[14];
    float* out = (float*)d_out;

    __nv_bfloat16 *adjh, *adjl, *Uh, *Ul, *Vh, *Vl, *Gh, *Gl, *Wh, *Wl;
    float* Cf;
    cudaGetSymbolAddress((void**)&adjh, g_adjh);
    cudaGetSymbolAddress((void**)&adjl, g_adjl);
    cudaGetSymbolAddress((void**)&Uh, g_Uh); cudaGetSymbolAddress((void**)&Ul, g_Ul);
    cudaGetSymbolAddress((void**)&Vh, g_Vh); cudaGetSymbolAddress((void**)&Vl, g_Vl);
    cudaGetSymbolAddress((void**)&Gh, g_Gh); cudaGetSymbolAddress((void**)&Gl, g_Gl);
    cudaGetSymbolAddress((void**)&Wh, g_Wh); cudaGetSymbolAddress((void**)&Wl, g_Wl);
    cudaGetSymbolAddress((void**)&Cf, g_Cf);

    cudaFuncSetAttribute(gemm_mma, cudaFuncAttributeMaxDynamicSharedMemorySize,
                         SMEM_SZ);
    dim3 blk(256);

    // ---- operand splits ----
    split_kernel<<<4096, blk>>>(adj, adjh, adjl, 8388608);
    split_kernel<<<1024, blk>>>(x, Uh, Ul, 2097152);
    split_kernel<<<256, blk>>>(W1,  Wh,           Wl,           65536);
    split_kernel<<<512, blk>>>(W2,  Wh + 262144,  Wl + 262144,  131072);
    split_kernel<<<256, blk>>>(W3,  Wh + 786432,  Wl + 786432,  65536);
    split_kernel<<<128, blk>>>(W4,  Wh + 1048576, Wl + 1048576, 32768);
    split_kernel<<<64,  blk>>>(cW1, Wh + 1179648, Wl + 1179648, 16384);

    const size_t ADJB = 1048576;
    const int M = BATCH * SEQ;

    // ---- Layer 1 (256 -> 512) ----
    gemm_mma<<<dim3(2, 8, 32), blk, SMEM_SZ>>>(
        adjh, adjl, ADJB, 1024, 1024, Uh, Ul, (size_t)1024 * 256, 256,
        nullptr, nullptr, 0, 0, nullptr, nullptr, 0,
        nullptr, nullptr, 0, Gh, Gl, nullptr, 256, 1024);
    gemm_mma<<<dim3(4, 256, 1), blk, SMEM_SZ>>>(
        Uh, Ul, 0, 256, 256, Wh, Wl, 0, 512,
        Gh, Gl, 256, 256, Wh + 131072, Wl + 131072, 512,
        b1, nullptr, 1, Vh, Vl, nullptr, 512, M);

    // ---- Layer 2 (512 -> 512) ----
    gemm_mma<<<dim3(4, 8, 32), blk, SMEM_SZ>>>(
        adjh, adjl, ADJB, 1024, 1024, Vh, Vl, (size_t)1024 * 512, 512,
        nullptr, nullptr, 0, 0, nullptr, nullptr, 0,
        nullptr, nullptr, 0, Gh, Gl, nullptr, 512, 1024);
    gemm_mma<<<dim3(4, 256, 1), blk, SMEM_SZ>>>(
        Vh, Vl, 0, 512, 512, Wh + 262144, Wl + 262144, 0, 512,
        Gh, Gl, 512, 512, Wh + 524288, Wl + 524288, 512,
        b2, nullptr, 1, Uh, Ul, nullptr, 512, M);

    // ---- Layer 3 (512 -> 256), reassociated:
    //   P = U @ Wb3  ;  h3 = relu(adj @ P + U @ Wt3 + b3)
    gemm_mma<<<dim3(2, 256, 1), blk, SMEM_SZ>>>(
        Uh, Ul, 0, 512, 512, Wh + 917504, Wl + 917504, 0, 256,
        nullptr, nullptr, 0, 0, nullptr, nullptr, 0,
        nullptr, nullptr, 0, Gh, Gl, nullptr, 256, M);
    gemm_mma<<<dim3(2, 8, 32), blk, SMEM_SZ>>>(
        adjh, adjl, ADJB, 1024, 1024, Gh, Gl, (size_t)1024 * 256, 256,
        Uh, Ul, 512, 512, Wh + 786432, Wl + 786432, 256,
        b3, nullptr, 1, Vh, Vl, nullptr, 256, 1024);

    // ---- Layer 4 (256 -> 256) ----
    gemm_mma<<<dim3(2, 8, 32), blk, SMEM_SZ>>>(
        adjh, adjl, ADJB, 1024, 1024, Vh, Vl, (size_t)1024 * 256, 256,
        nullptr, nullptr, 0, 0, nullptr, nullptr, 0,
        nullptr, nullptr, 0, Gh, Gl, nullptr, 256, 1024);
    gemm_mma<<<dim3(2, 256, 1), blk, SMEM_SZ>>>(
        Vh, Vl, 0, 256, 256, Wh + 1048576, Wl + 1048576, 0, 256,
        Gh, Gl, 256, 256, Wh + 1114112, Wl + 1114112, 256,
        b4, nullptr, 1, Uh, Ul, nullptr, 256, M);

    // ---- classifier: Linear + PReLU (fp32 out), then 256->2 head ----
    gemm_mma<<<dim3(2, 256, 1), blk, SMEM_SZ>>>(
        Uh, Ul, 0, 256, 256, Wh + 1179648, Wl + 1179648, 0, 256,
        nullptr, nullptr, 0, 0, nullptr, nullptr, 0,
        cb1, alpha, 2, nullptr, nullptr, Cf, 256, M);
    head_kernel<<<(M * 32 + 255) / 256, blk>>>(Cf, cW2, cb2, out, M);
}